// round 5
// baseline (speedup 1.0000x reference)
#include <cuda_runtime.h>
#include <cuda_bf16.h>
#include <math.h>
#include <stdint.h>

// Problem constants (fixed by setup_inputs)
#define NN 50000
#define EE 800000
#define DD 128
#define LL 2
#define NCHUNK ((NN + 1023) / 1024)

// ---------------- scratch (static __device__ globals; no allocation) ----------------
__device__ float g_Z[NN * DD];       // z gate (fp32)
__device__ float g_RH[NN * DD];      // r * h[l] (fp32, for agg1)
__device__ float g_HX[NN * DD];      // inp contribution to h_tilde preact (+ biases)
__device__ float g_bias[LL * 384];
__device__ float g_invdeg[NN];
__device__ int g_deg[NN];
__device__ int g_rowptr[NN + 1];
__device__ int g_cursor[NN];
__device__ int g_esrc[EE];
__device__ int g_chunksum[NCHUNK];
__device__ int g_chunkoff[NCHUNK];

// bf16 hi/lo split operands for HMMA GEMMs
__device__ __align__(16) __nv_bfloat16 g_inp_h[NN * DD], g_inp_l[NN * DD];
__device__ __align__(16) __nv_bfloat16 g_h_h[NN * DD],   g_h_l[NN * DD];
__device__ __align__(16) __nv_bfloat16 g_agga_h[NN * DD], g_agga_l[NN * DD];
__device__ __align__(16) __nv_bfloat16 g_aggb_h[NN * DD], g_aggb_l[NN * DD];
__device__ __align__(16) __nv_bfloat16 g_rh_h[NN * DD],  g_rh_l[NN * DD];
// transposed packed weights: W1T [L][384 n-rows][512 k], W2T [L][128 n-rows][256 k]
__device__ __align__(16) __nv_bfloat16 g_W1T_h[LL * 384 * 512], g_W1T_l[LL * 384 * 512];
__device__ __align__(16) __nv_bfloat16 g_W2T_h[LL * 128 * 256], g_W2T_l[LL * 128 * 256];

// ---------------- helpers ----------------
__device__ __forceinline__ uint32_t smem_u32(const void* p) {
    uint32_t a;
    asm("{ .reg .u64 t; cvta.to.shared.u64 t, %1; cvt.u32.u64 %0, t; }" : "=r"(a) : "l"(p));
    return a;
}
__device__ __forceinline__ void ldsm4(uint32_t* f, uint32_t addr) {
    asm volatile("ldmatrix.sync.aligned.m8n8.x4.shared.b16 {%0,%1,%2,%3}, [%4];"
                 : "=r"(f[0]), "=r"(f[1]), "=r"(f[2]), "=r"(f[3]) : "r"(addr));
}
__device__ __forceinline__ void mma16816(float* c, const uint32_t* a, uint32_t b0, uint32_t b1) {
    asm volatile(
        "mma.sync.aligned.m16n8k16.row.col.f32.bf16.bf16.f32 "
        "{%0,%1,%2,%3}, {%4,%5,%6,%7}, {%8,%9}, {%0,%1,%2,%3};"
        : "+f"(c[0]), "+f"(c[1]), "+f"(c[2]), "+f"(c[3])
        : "r"(a[0]), "r"(a[1]), "r"(a[2]), "r"(a[3]), "r"(b0), "r"(b1));
}
__device__ __forceinline__ void split_bf16(float v, __nv_bfloat16& h, __nv_bfloat16& l) {
    h = __float2bfloat16(v);
    l = __float2bfloat16(v - __bfloat162float(h));
}
__device__ __forceinline__ void store_split4(__nv_bfloat16* dh, __nv_bfloat16* dl, float4 v) {
    union { __nv_bfloat16 b[4]; unsigned long long u; } H, L;
    split_bf16(v.x, H.b[0], L.b[0]);
    split_bf16(v.y, H.b[1], L.b[1]);
    split_bf16(v.z, H.b[2], L.b[2]);
    split_bf16(v.w, H.b[3], L.b[3]);
    *(unsigned long long*)dh = H.u;
    *(unsigned long long*)dl = L.u;
}
__device__ __forceinline__ void store_split2(__nv_bfloat16* dh, __nv_bfloat16* dl, float a, float b) {
    union { __nv_bfloat16 b2[2]; uint32_t u; } H, L;
    split_bf16(a, H.b2[0], L.b2[0]);
    split_bf16(b, H.b2[1], L.b2[1]);
    *(uint32_t*)dh = H.u;
    *(uint32_t*)dl = L.u;
}
__device__ __forceinline__ float sigf(float x) { return 1.0f / (1.0f + expf(-x)); }

// SMEM tile geometry: 128 rows x 32 bf16, padded row stride 80B (conflict-free ldmatrix)
#define TROW 80
#define TBYTES (128 * TROW)   // 10240

// fetch a [128 x 32] bf16 tile into registers (2 x uint4 per thread, 256 threads)
__device__ __forceinline__ void fetch_tile(uint4* reg, const __nv_bfloat16* __restrict__ src,
                                           int stride, int row_base, int col_base,
                                           int row_limit, int t) {
#pragma unroll
    for (int i = 0; i < 2; i++) {
        int idx = t + i * 256;
        int r = idx >> 2, q = idx & 3;
        int gr = row_base + r;
        uint4 v = make_uint4(0u, 0u, 0u, 0u);
        if (gr < row_limit)
            v = *(const uint4*)(src + (size_t)gr * stride + col_base + q * 8);
        reg[i] = v;
    }
}
__device__ __forceinline__ void store_tile(char* st, const uint4* reg, int t) {
#pragma unroll
    for (int i = 0; i < 2; i++) {
        int idx = t + i * 256;
        int r = idx >> 2, q = idx & 3;
        *(uint4*)(st + r * TROW + q * 16) = reg[i];
    }
}

// ---------------- CSR construction ----------------
__global__ void k_zero() {
    int i = blockIdx.x * blockDim.x + threadIdx.x;
    if (i < NN) { g_deg[i] = 0; g_cursor[i] = 0; }
}
__global__ void k_count(const int* __restrict__ dst) {
    int e = blockIdx.x * blockDim.x + threadIdx.x;
    if (e < EE) atomicAdd(&g_deg[dst[e]], 1);
}
__global__ void k_scan_local() {
    int i = blockIdx.x * 1024 + threadIdx.x;
    int v = (i < NN) ? g_deg[i] : 0;
    int lane = threadIdx.x & 31, wid = threadIdx.x >> 5;
    int x = v;
#pragma unroll
    for (int o = 1; o < 32; o <<= 1) {
        int y = __shfl_up_sync(0xffffffffu, x, o);
        if (lane >= o) x += y;
    }
    __shared__ int ws[32];
    if (lane == 31) ws[wid] = x;
    __syncthreads();
    if (wid == 0) {
        int s = ws[lane];
        int xs = s;
#pragma unroll
        for (int o = 1; o < 32; o <<= 1) {
            int y = __shfl_up_sync(0xffffffffu, xs, o);
            if (lane >= o) xs += y;
        }
        ws[lane] = xs - s;
    }
    __syncthreads();
    int incl = x + ws[wid];
    if (i < NN) {
        g_rowptr[i] = incl - v;
        g_invdeg[i] = 1.0f / fmaxf((float)v, 1.0f);
    }
    if (threadIdx.x == 1023) g_chunksum[blockIdx.x] = incl;
}
__global__ void k_scan_mid() {
    if (threadIdx.x == 0) {
        int acc = 0;
        for (int c = 0; c < NCHUNK; c++) { g_chunkoff[c] = acc; acc += g_chunksum[c]; }
        g_rowptr[NN] = acc;
    }
}
__global__ void k_scan_add() {
    int i = blockIdx.x * 1024 + threadIdx.x;
    if (i < NN) g_rowptr[i] += g_chunkoff[blockIdx.x];
}
__global__ void k_fill(const int* __restrict__ src, const int* __restrict__ dst) {
    int e = blockIdx.x * blockDim.x + threadIdx.x;
    if (e < EE) {
        int d = dst[e];
        int p = atomicAdd(&g_cursor[d], 1);
        g_esrc[g_rowptr[d] + p] = src[e];
    }
}

// ---------------- weight packing (transposed, bf16 hi/lo) ----------------
__global__ void k_weights(const float* __restrict__ Wl, const float* __restrict__ Wr,
                          const float* __restrict__ b) {
    int i = blockIdx.x * blockDim.x + threadIdx.x;
    const int W1TN = LL * 384 * 512;
    const int W2TN = LL * 128 * 256;
    if (i < W1TN) {
        int l = i / (384 * 512);
        int rem = i % (384 * 512);
        int c = rem / 512, k = rem % 512;
        int cb = c >> 7, cc = c & 127;
        int s = k >> 7, kk = k & 127;
        float v = 0.0f;
        if (!(cb == 2 && s >= 2)) {
            int g = cb * 2 + (s >> 1);
            const float* W = (s & 1) ? Wr : Wl;
            v = W[(((size_t)l * 6 + g) * 128 + kk) * 128 + cc];
        }
        split_bf16(v, g_W1T_h[i], g_W1T_l[i]);
    } else if (i < W1TN + W2TN) {
        int j = i - W1TN;
        int l = j / (128 * 256);
        int rem = j % (128 * 256);
        int c = rem / 256, k = rem % 256;
        int s = k >> 7, kk = k & 127;
        const float* W = s ? Wr : Wl;
        float v = W[(((size_t)l * 6 + 5) * 128 + kk) * 128 + c];
        split_bf16(v, g_W2T_h[j], g_W2T_l[j]);
    } else if (i < W1TN + W2TN + LL * 384) {
        int j = i - W1TN - W2TN;
        int l = j / 384;
        int c = j % 384;
        int cb = c >> 7, cc = c & 127;
        g_bias[j] = b[(((size_t)l * 6 + cb * 2) * 128) + cc] +
                    b[(((size_t)l * 6 + cb * 2 + 1) * 128) + cc];
    }
}

// ---------------- fp32 -> bf16 hi/lo conversion ----------------
__global__ void k_conv(const float* __restrict__ src, int which) {
    int i = blockIdx.x * blockDim.x + threadIdx.x;
    if (i >= NN * DD / 4) return;
    float4 v = __ldg((const float4*)src + i);
    __nv_bfloat16* dh = which ? g_h_h : g_inp_h;
    __nv_bfloat16* dl = which ? g_h_l : g_inp_l;
    store_split4(dh + (size_t)i * 4, dl + (size_t)i * 4, v);
}

// ---------------- aggregation (warp per dst node, atomic-free via CSR) ----------------
__global__ void k_agg2(const float* __restrict__ A, const float* __restrict__ B) {
    int warp = (blockIdx.x * blockDim.x + threadIdx.x) >> 5;
    int lane = threadIdx.x & 31;
    if (warp >= NN) return;
    int e = g_rowptr[warp], end = g_rowptr[warp + 1];
    float4 aa = make_float4(0.f, 0.f, 0.f, 0.f);
    float4 ab = make_float4(0.f, 0.f, 0.f, 0.f);
    for (; e + 1 < end; e += 2) {
        int s0 = g_esrc[e], s1 = g_esrc[e + 1];
        float4 va0 = __ldg((const float4*)(A + (size_t)s0 * DD) + lane);
        float4 vb0 = __ldg((const float4*)(B + (size_t)s0 * DD) + lane);
        float4 va1 = __ldg((const float4*)(A + (size_t)s1 * DD) + lane);
        float4 vb1 = __ldg((const float4*)(B + (size_t)s1 * DD) + lane);
        aa.x += va0.x + va1.x; aa.y += va0.y + va1.y;
        aa.z += va0.z + va1.z; aa.w += va0.w + va1.w;
        ab.x += vb0.x + vb1.x; ab.y += vb0.y + vb1.y;
        ab.z += vb0.z + vb1.z; ab.w += vb0.w + vb1.w;
    }
    if (e < end) {
        int s0 = g_esrc[e];
        float4 va0 = __ldg((const float4*)(A + (size_t)s0 * DD) + lane);
        float4 vb0 = __ldg((const float4*)(B + (size_t)s0 * DD) + lane);
        aa.x += va0.x; aa.y += va0.y; aa.z += va0.z; aa.w += va0.w;
        ab.x += vb0.x; ab.y += vb0.y; ab.z += vb0.z; ab.w += vb0.w;
    }
    float sc = g_invdeg[warp];
    aa.x *= sc; aa.y *= sc; aa.z *= sc; aa.w *= sc;
    ab.x *= sc; ab.y *= sc; ab.z *= sc; ab.w *= sc;
    size_t o = (size_t)warp * DD + lane * 4;
    store_split4(g_agga_h + o, g_agga_l + o, aa);
    store_split4(g_aggb_h + o, g_aggb_l + o, ab);
}

__global__ void k_agg1() {
    int warp = (blockIdx.x * blockDim.x + threadIdx.x) >> 5;
    int lane = threadIdx.x & 31;
    if (warp >= NN) return;
    int e = g_rowptr[warp], end = g_rowptr[warp + 1];
    float4 aa = make_float4(0.f, 0.f, 0.f, 0.f);
    for (; e + 1 < end; e += 2) {
        int s0 = g_esrc[e], s1 = g_esrc[e + 1];
        float4 va0 = __ldg((const float4*)(g_RH + (size_t)s0 * DD) + lane);
        float4 va1 = __ldg((const float4*)(g_RH + (size_t)s1 * DD) + lane);
        aa.x += va0.x + va1.x; aa.y += va0.y + va1.y;
        aa.z += va0.z + va1.z; aa.w += va0.w + va1.w;
    }
    if (e < end) {
        int s0 = g_esrc[e];
        float4 va0 = __ldg((const float4*)(g_RH + (size_t)s0 * DD) + lane);
        aa.x += va0.x; aa.y += va0.y; aa.z += va0.z; aa.w += va0.w;
    }
    float sc = g_invdeg[warp];
    aa.x *= sc; aa.y *= sc; aa.z *= sc; aa.w *= sc;
    size_t o = (size_t)warp * DD + lane * 4;
    store_split4(g_agga_h + o, g_agga_l + o, aa);
}

// ---------------- HMMA GEMM core ----------------
// CTA: 256 thr (8 warps), tile 128x128; warp = 32 rows x 64 cols.
// SMEM: 4 tiles (Ah, Al, Bh, Bl), each 128x32 bf16 padded to 80B rows.
struct Frag {
    float acc[2][8][4];
};

__device__ __forceinline__ void gemm_chunk(char* sm, int t, float acc[2][8][4]) {
    uint32_t sA_h = smem_u32(sm);
    uint32_t sA_l = sA_h + TBYTES;
    uint32_t sB_h = sA_h + 2 * TBYTES;
    uint32_t sB_l = sA_h + 3 * TBYTES;
    int lane = t & 31, wid = t >> 5;
    int wm = wid & 3, wn = wid >> 2;
    uint32_t rsel = (uint32_t)(lane & 15) * TROW + (uint32_t)(lane >> 4) * 16;

#pragma unroll
    for (int kb = 0; kb < 2; kb++) {
        uint32_t ko = kb * 32;
        uint32_t aoff = (uint32_t)(wm * 32) * TROW + rsel + ko;
        uint32_t boff = (uint32_t)(wn * 64) * TROW + rsel + ko;
        uint32_t Ah[2][4], Bh[4][4];
        ldsm4(Ah[0], sA_h + aoff);
        ldsm4(Ah[1], sA_h + aoff + 16 * TROW);
#pragma unroll
        for (int ng = 0; ng < 4; ng++) ldsm4(Bh[ng], sB_h + boff + ng * 16 * TROW);
#pragma unroll
        for (int mt = 0; mt < 2; mt++)
#pragma unroll
            for (int nt = 0; nt < 8; nt++) {
                int ng = nt >> 1, o = nt & 1;
                mma16816(acc[mt][nt], Ah[mt], Bh[ng][o], Bh[ng][o + 2]);
            }
        {
            uint32_t Bl[4][4];
#pragma unroll
            for (int ng = 0; ng < 4; ng++) ldsm4(Bl[ng], sB_l + boff + ng * 16 * TROW);
#pragma unroll
            for (int mt = 0; mt < 2; mt++)
#pragma unroll
                for (int nt = 0; nt < 8; nt++) {
                    int ng = nt >> 1, o = nt & 1;
                    mma16816(acc[mt][nt], Ah[mt], Bl[ng][o], Bl[ng][o + 2]);
                }
        }
        {
            uint32_t Al[2][4];
            ldsm4(Al[0], sA_l + aoff);
            ldsm4(Al[1], sA_l + aoff + 16 * TROW);
#pragma unroll
            for (int mt = 0; mt < 2; mt++)
#pragma unroll
                for (int nt = 0; nt < 8; nt++) {
                    int ng = nt >> 1, o = nt & 1;
                    mma16816(acc[mt][nt], Al[mt], Bh[ng][o], Bh[ng][o + 2]);
                }
        }
    }
}

// ---------------- GEMM1: [N,512]x[512,384] fused z / r*h / hx ----------------
__global__ void __launch_bounds__(256, 2)
k_gemm1(const float* __restrict__ hl, int l) {
    __shared__ __align__(16) char sm[4 * TBYTES];
    int t = threadIdx.x;
    int row0 = blockIdx.y * 128;
    int cb = blockIdx.x;
    int col0 = cb * 128;

    const __nv_bfloat16* __restrict__ Wh = g_W1T_h + (size_t)l * 384 * 512;
    const __nv_bfloat16* __restrict__ Wlo = g_W1T_l + (size_t)l * 384 * 512;
    const __nv_bfloat16* segs_h[4] = { g_agga_h, g_inp_h, g_aggb_h, g_h_h };
    const __nv_bfloat16* segs_l[4] = { g_agga_l, g_inp_l, g_aggb_l, g_h_l };

    float acc[2][8][4];
#pragma unroll
    for (int i = 0; i < 2; i++)
#pragma unroll
        for (int j = 0; j < 8; j++)
#pragma unroll
            for (int q = 0; q < 4; q++) acc[i][j][q] = 0.0f;

    for (int c = 0; c < 16; c++) {
        int seg = c >> 2, colA = (c & 3) * 32, colB = c * 32;
        uint4 fAh[2], fAl[2], fBh[2], fBl[2];
        fetch_tile(fAh, segs_h[seg], 128, row0, colA, NN, t);
        fetch_tile(fAl, segs_l[seg], 128, row0, colA, NN, t);
        fetch_tile(fBh, Wh, 512, col0, colB, 1 << 30, t);
        fetch_tile(fBl, Wlo, 512, col0, colB, 1 << 30, t);
        __syncthreads();
        store_tile(sm, fAh, t);
        store_tile(sm + TBYTES, fAl, t);
        store_tile(sm + 2 * TBYTES, fBh, t);
        store_tile(sm + 3 * TBYTES, fBl, t);
        __syncthreads();
        gemm_chunk(sm, t, acc);
    }

    // epilogue
    int lane = t & 31, wid = t >> 5;
    int wm = wid & 3, wn = wid >> 2;
    const float* bias = g_bias + l * 384;
#pragma unroll
    for (int mt = 0; mt < 2; mt++)
#pragma unroll
        for (int nt = 0; nt < 8; nt++) {
            int row = row0 + wm * 32 + mt * 16 + (lane >> 2);
            int col = col0 + wn * 64 + nt * 8 + (lane & 3) * 2;
            float b0 = bias[col], b1 = bias[col + 1];
            int ccol = col & 127;
#pragma unroll
            for (int half = 0; half < 2; half++) {
                int r = row + half * 8;
                if (r >= NN) continue;
                float v0 = acc[mt][nt][half * 2 + 0] + b0;
                float v1 = acc[mt][nt][half * 2 + 1] + b1;
                size_t idx = (size_t)r * 128 + ccol;
                if (cb == 0) {
                    float2 z = make_float2(sigf(v0), sigf(v1));
                    *(float2*)(g_Z + idx) = z;
                } else if (cb == 1) {
                    float h0 = hl[idx], h1 = hl[idx + 1];
                    float rh0 = sigf(v0) * h0, rh1 = sigf(v1) * h1;
                    *(float2*)(g_RH + idx) = make_float2(rh0, rh1);
                    store_split2(g_rh_h + idx, g_rh_l + idx, rh0, rh1);
                } else {
                    *(float2*)(g_HX + idx) = make_float2(v0, v1);
                }
            }
        }
}

// ---------------- GEMM2: [N,256]x[256,128] fused GRU mix ----------------
__global__ void __launch_bounds__(256, 2)
k_gemm2(const float* __restrict__ hl, float* __restrict__ out, int l) {
    __shared__ __align__(16) char sm[4 * TBYTES];
    int t = threadIdx.x;
    int row0 = blockIdx.y * 128;

    const __nv_bfloat16* __restrict__ Wh = g_W2T_h + (size_t)l * 128 * 256;
    const __nv_bfloat16* __restrict__ Wlo = g_W2T_l + (size_t)l * 128 * 256;
    const __nv_bfloat16* segs_h[2] = { g_agga_h, g_rh_h };
    const __nv_bfloat16* segs_l[2] = { g_agga_l, g_rh_l };

    float acc[2][8][4];
#pragma unroll
    for (int i = 0; i < 2; i++)
#pragma unroll
        for (int j = 0; j < 8; j++)
#pragma unroll
            for (int q = 0; q < 4; q++) acc[i][j][q] = 0.0f;

    for (int c = 0; c < 8; c++) {
        int seg = c >> 2, colA = (c & 3) * 32, colB = c * 32;
        uint4 fAh[2], fAl[2], fBh[2], fBl[2];
        fetch_tile(fAh, segs_h[seg], 128, row0, colA, NN, t);
        fetch_tile(fAl, segs_l[seg], 128, row0, colA, NN, t);
        fetch_tile(fBh, Wh, 256, 0, colB, 1 << 30, t);
        fetch_tile(fBl, Wlo, 256, 0, colB, 1 << 30, t);
        __syncthreads();
        store_tile(sm, fAh, t);
        store_tile(sm + TBYTES, fAl, t);
        store_tile(sm + 2 * TBYTES, fBh, t);
        store_tile(sm + 3 * TBYTES, fBl, t);
        __syncthreads();
        gemm_chunk(sm, t, acc);
    }

    int lane = t & 31, wid = t >> 5;
    int wm = wid & 3, wn = wid >> 2;
#pragma unroll
    for (int mt = 0; mt < 2; mt++)
#pragma unroll
        for (int nt = 0; nt < 8; nt++) {
            int row = row0 + wm * 32 + mt * 16 + (lane >> 2);
            int col = wn * 64 + nt * 8 + (lane & 3) * 2;
#pragma unroll
            for (int half = 0; half < 2; half++) {
                int r = row + half * 8;
                if (r >= NN) continue;
                size_t idx = (size_t)r * 128 + col;
                float hx0 = g_HX[idx], hx1 = g_HX[idx + 1];
                float z0 = g_Z[idx], z1 = g_Z[idx + 1];
                float h0 = hl[idx], h1 = hl[idx + 1];
                float ht0 = tanhf(acc[mt][nt][half * 2 + 0] + hx0);
                float ht1 = tanhf(acc[mt][nt][half * 2 + 1] + hx1);
                float o0 = z0 * h0 + (1.0f - z0) * ht0;
                float o1 = z1 * h1 + (1.0f - z1) * ht1;
                *(float2*)(out + idx) = make_float2(o0, o1);
                store_split2(g_inp_h + idx, g_inp_l + idx, o0, o1);
            }
        }
}

// ---------------- launch ----------------
extern "C" void kernel_launch(void* const* d_in, const int* in_sizes, int n_in,
                              void* d_out, int out_size) {
    const float* x  = (const float*)d_in[0];
    const float* h  = (const float*)d_in[1];
    const float* Wl = (const float*)d_in[2];
    const float* Wr = (const float*)d_in[3];
    const float* b  = (const float*)d_in[4];
    const int* src  = (const int*)d_in[5];
    const int* dst  = (const int*)d_in[6];
    float* out = (float*)d_out;

    // CSR build
    k_zero<<<(NN + 255) / 256, 256>>>();
    k_count<<<(EE + 255) / 256, 256>>>(dst);
    k_scan_local<<<NCHUNK, 1024>>>();
    k_scan_mid<<<1, 32>>>();
    k_scan_add<<<NCHUNK, 1024>>>();
    k_fill<<<(EE + 255) / 256, 256>>>(src, dst);

    // weights (transposed bf16 hi/lo) + biases
    const int WTOT = LL * 384 * 512 + LL * 128 * 256 + LL * 384;
    k_weights<<<(WTOT + 255) / 256, 256>>>(Wl, Wr, b);

    // x -> inp hi/lo for layer 0
    k_conv<<<(NN * DD / 4 + 255) / 256, 256>>>(x, 0);

    const int ROWT = (NN + 127) / 128;
    for (int l = 0; l < LL; l++) {
        const float* inp = (l == 0) ? x : (out + (size_t)(l - 1) * NN * DD);
        const float* hl = h + (size_t)l * NN * DD;
        k_conv<<<(NN * DD / 4 + 255) / 256, 256>>>(hl, 1);
        k_agg2<<<(NN * 32 + 255) / 256, 256>>>(inp, hl);
        dim3 g1(3, ROWT);
        k_gemm1<<<g1, 256>>>(hl, l);
        k_agg1<<<(NN * 32 + 255) / 256, 256>>>();
        dim3 g2(1, ROWT);
        k_gemm2<<<g2, 256>>>(hl, out + (size_t)l * NN * DD, l);
    }
}

// round 6
// speedup vs baseline: 1.0892x; 1.0892x over previous
#include <cuda_runtime.h>
#include <cuda_bf16.h>
#include <math.h>
#include <stdint.h>

// Problem constants (fixed by setup_inputs)
#define NN 50000
#define EE 800000
#define DD 128
#define LL 2
#define NCHUNK ((NN + 1023) / 1024)

// ---------------- scratch (static __device__ globals; no allocation) ----------------
__device__ float g_Z[NN * DD];
__device__ float g_RH[NN * DD];
__device__ float g_HX[NN * DD];
__device__ float g_bias[LL * 384];
__device__ float g_invdeg[NN];
__device__ int g_deg[NN];
__device__ int g_rowptr[NN + 1];
__device__ int g_cursor[NN];
__device__ int g_esrc[EE];
__device__ int g_chunksum[NCHUNK];
__device__ int g_chunkoff[NCHUNK];

__device__ __align__(16) __nv_bfloat16 g_inp_h[NN * DD], g_inp_l[NN * DD];
__device__ __align__(16) __nv_bfloat16 g_h_h[NN * DD],   g_h_l[NN * DD];
__device__ __align__(16) __nv_bfloat16 g_agga_h[NN * DD], g_agga_l[NN * DD];
__device__ __align__(16) __nv_bfloat16 g_aggb_h[NN * DD], g_aggb_l[NN * DD];
__device__ __align__(16) __nv_bfloat16 g_rh_h[NN * DD],  g_rh_l[NN * DD];
__device__ __align__(16) __nv_bfloat16 g_W1T_h[LL * 384 * 512], g_W1T_l[LL * 384 * 512];
__device__ __align__(16) __nv_bfloat16 g_W2T_h[LL * 128 * 256], g_W2T_l[LL * 128 * 256];

// ---------------- helpers ----------------
__device__ __forceinline__ uint32_t smem_u32(const void* p) {
    uint32_t a;
    asm("{ .reg .u64 t; cvta.to.shared.u64 t, %1; cvt.u32.u64 %0, t; }" : "=r"(a) : "l"(p));
    return a;
}
__device__ __forceinline__ void ldsm4(uint32_t* f, uint32_t addr) {
    asm volatile("ldmatrix.sync.aligned.m8n8.x4.shared.b16 {%0,%1,%2,%3}, [%4];"
                 : "=r"(f[0]), "=r"(f[1]), "=r"(f[2]), "=r"(f[3]) : "r"(addr));
}
__device__ __forceinline__ void mma16816(float* c, const uint32_t* a, uint32_t b0, uint32_t b1) {
    asm volatile(
        "mma.sync.aligned.m16n8k16.row.col.f32.bf16.bf16.f32 "
        "{%0,%1,%2,%3}, {%4,%5,%6,%7}, {%8,%9}, {%0,%1,%2,%3};"
        : "+f"(c[0]), "+f"(c[1]), "+f"(c[2]), "+f"(c[3])
        : "r"(a[0]), "r"(a[1]), "r"(a[2]), "r"(a[3]), "r"(b0), "r"(b1));
}
#define CPA_COMMIT() asm volatile("cp.async.commit_group;" ::: "memory")
#define CPA_WAIT1()  asm volatile("cp.async.wait_group 1;" ::: "memory")

__device__ __forceinline__ void split_bf16(float v, __nv_bfloat16& h, __nv_bfloat16& l) {
    h = __float2bfloat16(v);
    l = __float2bfloat16(v - __bfloat162float(h));
}
__device__ __forceinline__ void store_split4(__nv_bfloat16* dh, __nv_bfloat16* dl, float4 v) {
    union { __nv_bfloat16 b[4]; unsigned long long u; } H, L;
    split_bf16(v.x, H.b[0], L.b[0]);
    split_bf16(v.y, H.b[1], L.b[1]);
    split_bf16(v.z, H.b[2], L.b[2]);
    split_bf16(v.w, H.b[3], L.b[3]);
    *(unsigned long long*)dh = H.u;
    *(unsigned long long*)dl = L.u;
}
__device__ __forceinline__ void store_split2(__nv_bfloat16* dh, __nv_bfloat16* dl, float a, float b) {
    union { __nv_bfloat16 b2[2]; uint32_t u; } H, L;
    split_bf16(a, H.b2[0], L.b2[0]);
    split_bf16(b, H.b2[1], L.b2[1]);
    *(uint32_t*)dh = H.u;
    *(uint32_t*)dl = L.u;
}
__device__ __forceinline__ float sigf(float x) { return 1.0f / (1.0f + expf(-x)); }

// SMEM tile geometry: 128 rows x 32 bf16, padded row stride 80B (conflict-free ldmatrix)
#define TROW 80
#define TBYTES (128 * TROW)        // 10240
#define STAGE (4 * TBYTES)         // Ah,Al,Bh,Bl
#define GSMEM (2 * STAGE)          // 81920

// async load of a [128 x 32] bf16 tile into padded SMEM; OOB rows -> zero fill
__device__ __forceinline__ void tile_async(uint32_t dst, const __nv_bfloat16* __restrict__ src,
                                           int stride, int row_base, int col_base,
                                           int row_limit, int t) {
#pragma unroll
    for (int i = 0; i < 2; i++) {
        int idx = t + i * 256;
        int r = idx >> 2, q = idx & 3;
        int gr = row_base + r;
        bool ok = gr < row_limit;
        int grc = ok ? gr : 0;
        const void* s = src + (size_t)grc * stride + col_base + q * 8;
        int sz = ok ? 16 : 0;
        asm volatile("cp.async.cg.shared.global [%0], [%1], 16, %2;"
                     :: "r"(dst + (uint32_t)(r * TROW + q * 16)), "l"(s), "r"(sz) : "memory");
    }
}

// ---------------- CSR construction ----------------
__global__ void k_zero() {
    int i = blockIdx.x * blockDim.x + threadIdx.x;
    if (i < NN) { g_deg[i] = 0; g_cursor[i] = 0; }
}
__global__ void k_count(const int* __restrict__ dst) {
    int e = blockIdx.x * blockDim.x + threadIdx.x;
    if (e < EE) atomicAdd(&g_deg[dst[e]], 1);
}
__global__ void k_scan_local() {
    int i = blockIdx.x * 1024 + threadIdx.x;
    int v = (i < NN) ? g_deg[i] : 0;
    int lane = threadIdx.x & 31, wid = threadIdx.x >> 5;
    int x = v;
#pragma unroll
    for (int o = 1; o < 32; o <<= 1) {
        int y = __shfl_up_sync(0xffffffffu, x, o);
        if (lane >= o) x += y;
    }
    __shared__ int ws[32];
    if (lane == 31) ws[wid] = x;
    __syncthreads();
    if (wid == 0) {
        int s = ws[lane];
        int xs = s;
#pragma unroll
        for (int o = 1; o < 32; o <<= 1) {
            int y = __shfl_up_sync(0xffffffffu, xs, o);
            if (lane >= o) xs += y;
        }
        ws[lane] = xs - s;
    }
    __syncthreads();
    int incl = x + ws[wid];
    if (i < NN) {
        g_rowptr[i] = incl - v;
        g_invdeg[i] = 1.0f / fmaxf((float)v, 1.0f);
    }
    if (threadIdx.x == 1023) g_chunksum[blockIdx.x] = incl;
}
__global__ void k_scan_mid() {
    if (threadIdx.x == 0) {
        int acc = 0;
        for (int c = 0; c < NCHUNK; c++) { g_chunkoff[c] = acc; acc += g_chunksum[c]; }
        g_rowptr[NN] = acc;
    }
}
__global__ void k_scan_add() {
    int i = blockIdx.x * 1024 + threadIdx.x;
    if (i < NN) g_rowptr[i] += g_chunkoff[blockIdx.x];
}
__global__ void k_fill(const int* __restrict__ src, const int* __restrict__ dst) {
    int e = blockIdx.x * blockDim.x + threadIdx.x;
    if (e < EE) {
        int d = dst[e];
        int p = atomicAdd(&g_cursor[d], 1);
        g_esrc[g_rowptr[d] + p] = src[e];
    }
}

// ---------------- weight packing (transposed, bf16 hi/lo) ----------------
__global__ void k_weights(const float* __restrict__ Wl, const float* __restrict__ Wr,
                          const float* __restrict__ b) {
    int i = blockIdx.x * blockDim.x + threadIdx.x;
    const int W1TN = LL * 384 * 512;
    const int W2TN = LL * 128 * 256;
    if (i < W1TN) {
        int l = i / (384 * 512);
        int rem = i % (384 * 512);
        int c = rem / 512, k = rem % 512;
        int cb = c >> 7, cc = c & 127;
        int s = k >> 7, kk = k & 127;
        float v = 0.0f;
        if (!(cb == 2 && s >= 2)) {
            int g = cb * 2 + (s >> 1);
            const float* W = (s & 1) ? Wr : Wl;
            v = W[(((size_t)l * 6 + g) * 128 + kk) * 128 + cc];
        }
        split_bf16(v, g_W1T_h[i], g_W1T_l[i]);
    } else if (i < W1TN + W2TN) {
        int j = i - W1TN;
        int l = j / (128 * 256);
        int rem = j % (128 * 256);
        int c = rem / 256, k = rem % 256;
        int s = k >> 7, kk = k & 127;
        const float* W = s ? Wr : Wl;
        float v = W[(((size_t)l * 6 + 5) * 128 + kk) * 128 + c];
        split_bf16(v, g_W2T_h[j], g_W2T_l[j]);
    } else if (i < W1TN + W2TN + LL * 384) {
        int j = i - W1TN - W2TN;
        int l = j / 384;
        int c = j % 384;
        int cb = c >> 7, cc = c & 127;
        g_bias[j] = b[(((size_t)l * 6 + cb * 2) * 128) + cc] +
                    b[(((size_t)l * 6 + cb * 2 + 1) * 128) + cc];
    }
}

// ---------------- fp32 -> bf16 hi/lo conversion (x only; h fused into agg2) ----------------
__global__ void k_conv(const float* __restrict__ src) {
    int i = blockIdx.x * blockDim.x + threadIdx.x;
    if (i >= NN * DD / 4) return;
    float4 v = __ldg((const float4*)src + i);
    store_split4(g_inp_h + (size_t)i * 4, g_inp_l + (size_t)i * 4, v);
}

// ---------------- aggregation (warp per dst node, atomic-free via CSR) ----------------
// also emits hi/lo split of hl row (fuses k_conv for h)
__global__ void k_agg2(const float* __restrict__ A, const float* __restrict__ B) {
    int warp = (blockIdx.x * blockDim.x + threadIdx.x) >> 5;
    int lane = threadIdx.x & 31;
    if (warp >= NN) return;
    int e = g_rowptr[warp], end = g_rowptr[warp + 1];
    float4 aa = make_float4(0.f, 0.f, 0.f, 0.f);
    float4 ab = make_float4(0.f, 0.f, 0.f, 0.f);
    for (; e + 1 < end; e += 2) {
        int s0 = g_esrc[e], s1 = g_esrc[e + 1];
        float4 va0 = __ldg((const float4*)(A + (size_t)s0 * DD) + lane);
        float4 vb0 = __ldg((const float4*)(B + (size_t)s0 * DD) + lane);
        float4 va1 = __ldg((const float4*)(A + (size_t)s1 * DD) + lane);
        float4 vb1 = __ldg((const float4*)(B + (size_t)s1 * DD) + lane);
        aa.x += va0.x + va1.x; aa.y += va0.y + va1.y;
        aa.z += va0.z + va1.z; aa.w += va0.w + va1.w;
        ab.x += vb0.x + vb1.x; ab.y += vb0.y + vb1.y;
        ab.z += vb0.z + vb1.z; ab.w += vb0.w + vb1.w;
    }
    if (e < end) {
        int s0 = g_esrc[e];
        float4 va0 = __ldg((const float4*)(A + (size_t)s0 * DD) + lane);
        float4 vb0 = __ldg((const float4*)(B + (size_t)s0 * DD) + lane);
        aa.x += va0.x; aa.y += va0.y; aa.z += va0.z; aa.w += va0.w;
        ab.x += vb0.x; ab.y += vb0.y; ab.z += vb0.z; ab.w += vb0.w;
    }
    float sc = g_invdeg[warp];
    aa.x *= sc; aa.y *= sc; aa.z *= sc; aa.w *= sc;
    ab.x *= sc; ab.y *= sc; ab.z *= sc; ab.w *= sc;
    size_t o = (size_t)warp * DD + lane * 4;
    store_split4(g_agga_h + o, g_agga_l + o, aa);
    store_split4(g_aggb_h + o, g_aggb_l + o, ab);
    // fused: split hl row for GEMM1's B-side operand segments
    float4 hv = __ldg((const float4*)(B + (size_t)warp * DD) + lane);
    store_split4(g_h_h + o, g_h_l + o, hv);
}

__global__ void k_agg1() {
    int warp = (blockIdx.x * blockDim.x + threadIdx.x) >> 5;
    int lane = threadIdx.x & 31;
    if (warp >= NN) return;
    int e = g_rowptr[warp], end = g_rowptr[warp + 1];
    float4 aa = make_float4(0.f, 0.f, 0.f, 0.f);
    for (; e + 1 < end; e += 2) {
        int s0 = g_esrc[e], s1 = g_esrc[e + 1];
        float4 va0 = __ldg((const float4*)(g_RH + (size_t)s0 * DD) + lane);
        float4 va1 = __ldg((const float4*)(g_RH + (size_t)s1 * DD) + lane);
        aa.x += va0.x + va1.x; aa.y += va0.y + va1.y;
        aa.z += va0.z + va1.z; aa.w += va0.w + va1.w;
    }
    if (e < end) {
        int s0 = g_esrc[e];
        float4 va0 = __ldg((const float4*)(g_RH + (size_t)s0 * DD) + lane);
        aa.x += va0.x; aa.y += va0.y; aa.z += va0.z; aa.w += va0.w;
    }
    float sc = g_invdeg[warp];
    aa.x *= sc; aa.y *= sc; aa.z *= sc; aa.w *= sc;
    size_t o = (size_t)warp * DD + lane * 4;
    store_split4(g_agga_h + o, g_agga_l + o, aa);
}

// ---------------- HMMA GEMM core ----------------
__device__ __forceinline__ void gemm_chunk(uint32_t sA_h, int t, float acc[2][8][4]) {
    uint32_t sA_l = sA_h + TBYTES;
    uint32_t sB_h = sA_h + 2 * TBYTES;
    uint32_t sB_l = sA_h + 3 * TBYTES;
    int lane = t & 31, wid = t >> 5;
    int wm = wid & 3, wn = wid >> 2;
    uint32_t rsel = (uint32_t)(lane & 15) * TROW + (uint32_t)(lane >> 4) * 16;

#pragma unroll
    for (int kb = 0; kb < 2; kb++) {
        uint32_t ko = kb * 32;
        uint32_t aoff = (uint32_t)(wm * 32) * TROW + rsel + ko;
        uint32_t boff = (uint32_t)(wn * 64) * TROW + rsel + ko;
        uint32_t Ah[2][4], Bh[4][4];
        ldsm4(Ah[0], sA_h + aoff);
        ldsm4(Ah[1], sA_h + aoff + 16 * TROW);
#pragma unroll
        for (int ng = 0; ng < 4; ng++) ldsm4(Bh[ng], sB_h + boff + ng * 16 * TROW);
#pragma unroll
        for (int mt = 0; mt < 2; mt++)
#pragma unroll
            for (int nt = 0; nt < 8; nt++) {
                int ng = nt >> 1, o = nt & 1;
                mma16816(acc[mt][nt], Ah[mt], Bh[ng][o], Bh[ng][o + 2]);
            }
        {
            uint32_t Bl[4][4];
#pragma unroll
            for (int ng = 0; ng < 4; ng++) ldsm4(Bl[ng], sB_l + boff + ng * 16 * TROW);
#pragma unroll
            for (int mt = 0; mt < 2; mt++)
#pragma unroll
                for (int nt = 0; nt < 8; nt++) {
                    int ng = nt >> 1, o = nt & 1;
                    mma16816(acc[mt][nt], Ah[mt], Bl[ng][o], Bl[ng][o + 2]);
                }
        }
        {
            uint32_t Al[2][4];
            ldsm4(Al[0], sA_l + aoff);
            ldsm4(Al[1], sA_l + aoff + 16 * TROW);
#pragma unroll
            for (int mt = 0; mt < 2; mt++)
#pragma unroll
                for (int nt = 0; nt < 8; nt++) {
                    int ng = nt >> 1, o = nt & 1;
                    mma16816(acc[mt][nt], Al[mt], Bh[ng][o], Bh[ng][o + 2]);
                }
        }
    }
}

// ---------------- GEMM1: [N,512]x[512,384] fused z / r*h / hx, cp.async pipelined ----------------
__global__ void __launch_bounds__(256, 2)
k_gemm1(const float* __restrict__ hl, int l) {
    extern __shared__ __align__(16) char smdyn[];
    uint32_t sb = smem_u32(smdyn);
    int t = threadIdx.x;
    int row0 = blockIdx.y * 128;
    int cb = blockIdx.x;
    int col0 = cb * 128;

    const __nv_bfloat16* __restrict__ Wh = g_W1T_h + (size_t)l * 384 * 512;
    const __nv_bfloat16* __restrict__ Wlo = g_W1T_l + (size_t)l * 384 * 512;
    const __nv_bfloat16* segs_h[4] = { g_agga_h, g_inp_h, g_aggb_h, g_h_h };
    const __nv_bfloat16* segs_l[4] = { g_agga_l, g_inp_l, g_aggb_l, g_h_l };

    float acc[2][8][4];
#pragma unroll
    for (int i = 0; i < 2; i++)
#pragma unroll
        for (int j = 0; j < 8; j++)
#pragma unroll
            for (int q = 0; q < 4; q++) acc[i][j][q] = 0.0f;

    // prologue: chunk 0
    {
        uint32_t buf = sb;
        tile_async(buf,              segs_h[0], 128, row0, 0, NN, t);
        tile_async(buf + TBYTES,     segs_l[0], 128, row0, 0, NN, t);
        tile_async(buf + 2 * TBYTES, Wh,  512, col0, 0, 1 << 30, t);
        tile_async(buf + 3 * TBYTES, Wlo, 512, col0, 0, 1 << 30, t);
        CPA_COMMIT();
    }
    for (int c = 0; c < 16; c++) {
        if (c + 1 < 16) {
            int cn = c + 1;
            int seg = cn >> 2, colA = (cn & 3) * 32, colB = cn * 32;
            uint32_t buf = sb + (cn & 1) * STAGE;
            tile_async(buf,              segs_h[seg], 128, row0, colA, NN, t);
            tile_async(buf + TBYTES,     segs_l[seg], 128, row0, colA, NN, t);
            tile_async(buf + 2 * TBYTES, Wh,  512, col0, colB, 1 << 30, t);
            tile_async(buf + 3 * TBYTES, Wlo, 512, col0, colB, 1 << 30, t);
        }
        CPA_COMMIT();
        CPA_WAIT1();
        __syncthreads();
        gemm_chunk(sb + (c & 1) * STAGE, t, acc);
        __syncthreads();
    }

    // epilogue
    int lane = t & 31, wid = t >> 5;
    int wm = wid & 3, wn = wid >> 2;
    const float* bias = g_bias + l * 384;
#pragma unroll
    for (int mt = 0; mt < 2; mt++)
#pragma unroll
        for (int nt = 0; nt < 8; nt++) {
            int row = row0 + wm * 32 + mt * 16 + (lane >> 2);
            int col = col0 + wn * 64 + nt * 8 + (lane & 3) * 2;
            float b0 = bias[col], b1 = bias[col + 1];
            int ccol = col & 127;
#pragma unroll
            for (int half = 0; half < 2; half++) {
                int r = row + half * 8;
                if (r >= NN) continue;
                float v0 = acc[mt][nt][half * 2 + 0] + b0;
                float v1 = acc[mt][nt][half * 2 + 1] + b1;
                size_t idx = (size_t)r * 128 + ccol;
                if (cb == 0) {
                    float2 z = make_float2(sigf(v0), sigf(v1));
                    *(float2*)(g_Z + idx) = z;
                } else if (cb == 1) {
                    float h0 = hl[idx], h1 = hl[idx + 1];
                    float rh0 = sigf(v0) * h0, rh1 = sigf(v1) * h1;
                    *(float2*)(g_RH + idx) = make_float2(rh0, rh1);
                    store_split2(g_rh_h + idx, g_rh_l + idx, rh0, rh1);
                } else {
                    *(float2*)(g_HX + idx) = make_float2(v0, v1);
                }
            }
        }
}

// ---------------- GEMM2: [N,256]x[256,128] fused GRU mix, cp.async pipelined ----------------
__global__ void __launch_bounds__(256, 2)
k_gemm2(const float* __restrict__ hl, float* __restrict__ out, int l) {
    extern __shared__ __align__(16) char smdyn[];
    uint32_t sb = smem_u32(smdyn);
    int t = threadIdx.x;
    int row0 = blockIdx.y * 128;

    const __nv_bfloat16* __restrict__ Wh = g_W2T_h + (size_t)l * 128 * 256;
    const __nv_bfloat16* __restrict__ Wlo = g_W2T_l + (size_t)l * 128 * 256;
    const __nv_bfloat16* segs_h[2] = { g_agga_h, g_rh_h };
    const __nv_bfloat16* segs_l[2] = { g_agga_l, g_rh_l };

    float acc[2][8][4];
#pragma unroll
    for (int i = 0; i < 2; i++)
#pragma unroll
        for (int j = 0; j < 8; j++)
#pragma unroll
            for (int q = 0; q < 4; q++) acc[i][j][q] = 0.0f;

    {
        uint32_t buf = sb;
        tile_async(buf,              segs_h[0], 128, row0, 0, NN, t);
        tile_async(buf + TBYTES,     segs_l[0], 128, row0, 0, NN, t);
        tile_async(buf + 2 * TBYTES, Wh,  256, 0, 0, 1 << 30, t);
        tile_async(buf + 3 * TBYTES, Wlo, 256, 0, 0, 1 << 30, t);
        CPA_COMMIT();
    }
    for (int c = 0; c < 8; c++) {
        if (c + 1 < 8) {
            int cn = c + 1;
            int seg = cn >> 2, colA = (cn & 3) * 32, colB = cn * 32;
            uint32_t buf = sb + (cn & 1) * STAGE;
            tile_async(buf,              segs_h[seg], 128, row0, colA, NN, t);
            tile_async(buf + TBYTES,     segs_l[seg], 128, row0, colA, NN, t);
            tile_async(buf + 2 * TBYTES, Wh,  256, 0, colB, 1 << 30, t);
            tile_async(buf + 3 * TBYTES, Wlo, 256, 0, colB, 1 << 30, t);
        }
        CPA_COMMIT();
        CPA_WAIT1();
        __syncthreads();
        gemm_chunk(sb + (c & 1) * STAGE, t, acc);
        __syncthreads();
    }

    int lane = t & 31, wid = t >> 5;
    int wm = wid & 3, wn = wid >> 2;
#pragma unroll
    for (int mt = 0; mt < 2; mt++)
#pragma unroll
        for (int nt = 0; nt < 8; nt++) {
            int row = row0 + wm * 32 + mt * 16 + (lane >> 2);
            int col = wn * 64 + nt * 8 + (lane & 3) * 2;
#pragma unroll
            for (int half = 0; half < 2; half++) {
                int r = row + half * 8;
                if (r >= NN) continue;
                size_t idx = (size_t)r * 128 + col;
                float hx0 = g_HX[idx], hx1 = g_HX[idx + 1];
                float z0 = g_Z[idx], z1 = g_Z[idx + 1];
                float h0 = hl[idx], h1 = hl[idx + 1];
                float ht0 = tanhf(acc[mt][nt][half * 2 + 0] + hx0);
                float ht1 = tanhf(acc[mt][nt][half * 2 + 1] + hx1);
                float o0 = z0 * h0 + (1.0f - z0) * ht0;
                float o1 = z1 * h1 + (1.0f - z1) * ht1;
                *(float2*)(out + idx) = make_float2(o0, o1);
                store_split2(g_inp_h + idx, g_inp_l + idx, o0, o1);
            }
        }
}

// ---------------- launch ----------------
extern "C" void kernel_launch(void* const* d_in, const int* in_sizes, int n_in,
                              void* d_out, int out_size) {
    const float* x  = (const float*)d_in[0];
    const float* h  = (const float*)d_in[1];
    const float* Wl = (const float*)d_in[2];
    const float* Wr = (const float*)d_in[3];
    const float* b  = (const float*)d_in[4];
    const int* src  = (const int*)d_in[5];
    const int* dst  = (const int*)d_in[6];
    float* out = (float*)d_out;

    cudaFuncSetAttribute(k_gemm1, cudaFuncAttributeMaxDynamicSharedMemorySize, GSMEM);
    cudaFuncSetAttribute(k_gemm2, cudaFuncAttributeMaxDynamicSharedMemorySize, GSMEM);

    // CSR build
    k_zero<<<(NN + 255) / 256, 256>>>();
    k_count<<<(EE + 255) / 256, 256>>>(dst);
    k_scan_local<<<NCHUNK, 1024>>>();
    k_scan_mid<<<1, 32>>>();
    k_scan_add<<<NCHUNK, 1024>>>();
    k_fill<<<(EE + 255) / 256, 256>>>(src, dst);

    // weights (transposed bf16 hi/lo) + biases
    const int WTOT = LL * 384 * 512 + LL * 128 * 256 + LL * 384;
    k_weights<<<(WTOT + 255) / 256, 256>>>(Wl, Wr, b);

    // x -> inp hi/lo for layer 0
    k_conv<<<(NN * DD / 4 + 255) / 256, 256>>>(x);

    const int ROWT = (NN + 127) / 128;
    for (int l = 0; l < LL; l++) {
        const float* inp = (l == 0) ? x : (out + (size_t)(l - 1) * NN * DD);
        const float* hl = h + (size_t)l * NN * DD;
        k_agg2<<<(NN * 32 + 255) / 256, 256>>>(inp, hl);
        dim3 g1(3, ROWT);
        k_gemm1<<<g1, 256, GSMEM>>>(hl, l);
        k_agg1<<<(NN * 32 + 255) / 256, 256>>>();
        dim3 g2(1, ROWT);
        k_gemm2<<<g2, 256, GSMEM>>>(hl, out + (size_t)l * NN * DD, l);
    }
}

// round 7
// speedup vs baseline: 1.1255x; 1.0333x over previous
#include <cuda_runtime.h>
#include <cuda_bf16.h>
#include <math.h>
#include <stdint.h>

// Problem constants (fixed by setup_inputs)
#define NN 50000
#define EE 800000
#define DD 128
#define LL 2
#define NCHUNK ((NN + 1023) / 1024)

// ---------------- scratch (static __device__ globals; no allocation) ----------------
__device__ float g_Z[NN * DD];
__device__ float g_RH[NN * DD];
__device__ float g_HX[NN * DD];
__device__ float g_bias[LL * 384];
__device__ float g_invdeg[NN];
__device__ int g_deg[NN];
__device__ int g_rowptr[NN + 1];
__device__ int g_cursor[NN];
__device__ int g_esrc[EE];
__device__ int g_chunksum[NCHUNK];
__device__ int g_chunkoff[NCHUNK];

__device__ __align__(16) __nv_bfloat16 g_inp_h[NN * DD], g_inp_l[NN * DD];
__device__ __align__(16) __nv_bfloat16 g_h_h[NN * DD],   g_h_l[NN * DD];
__device__ __align__(16) __nv_bfloat16 g_agga_h[NN * DD], g_agga_l[NN * DD];
__device__ __align__(16) __nv_bfloat16 g_aggb_h[NN * DD], g_aggb_l[NN * DD];
__device__ __align__(16) __nv_bfloat16 g_rh_h[NN * DD],  g_rh_l[NN * DD];
__device__ __align__(16) __nv_bfloat16 g_W1T_h[LL * 384 * 512], g_W1T_l[LL * 384 * 512];
__device__ __align__(16) __nv_bfloat16 g_W2T_h[LL * 128 * 256], g_W2T_l[LL * 128 * 256];

// ---------------- helpers ----------------
__device__ __forceinline__ uint32_t smem_u32(const void* p) {
    uint32_t a;
    asm("{ .reg .u64 t; cvta.to.shared.u64 t, %1; cvt.u32.u64 %0, t; }" : "=r"(a) : "l"(p));
    return a;
}
__device__ __forceinline__ void ldsm4(uint32_t* f, uint32_t addr) {
    asm volatile("ldmatrix.sync.aligned.m8n8.x4.shared.b16 {%0,%1,%2,%3}, [%4];"
                 : "=r"(f[0]), "=r"(f[1]), "=r"(f[2]), "=r"(f[3]) : "r"(addr));
}
__device__ __forceinline__ void mma16816(float* c, const uint32_t* a, uint32_t b0, uint32_t b1) {
    asm volatile(
        "mma.sync.aligned.m16n8k16.row.col.f32.bf16.bf16.f32 "
        "{%0,%1,%2,%3}, {%4,%5,%6,%7}, {%8,%9}, {%0,%1,%2,%3};"
        : "+f"(c[0]), "+f"(c[1]), "+f"(c[2]), "+f"(c[3])
        : "r"(a[0]), "r"(a[1]), "r"(a[2]), "r"(a[3]), "r"(b0), "r"(b1));
}
#define CPA_COMMIT() asm volatile("cp.async.commit_group;" ::: "memory")
#define CPA_WAIT1()  asm volatile("cp.async.wait_group 1;" ::: "memory")

__device__ __forceinline__ void split_bf16(float v, __nv_bfloat16& h, __nv_bfloat16& l) {
    h = __float2bfloat16(v);
    l = __float2bfloat16(v - __bfloat162float(h));
}
__device__ __forceinline__ void store_split4(__nv_bfloat16* dh, __nv_bfloat16* dl, float4 v) {
    union { __nv_bfloat16 b[4]; unsigned long long u; } H, L;
    split_bf16(v.x, H.b[0], L.b[0]);
    split_bf16(v.y, H.b[1], L.b[1]);
    split_bf16(v.z, H.b[2], L.b[2]);
    split_bf16(v.w, H.b[3], L.b[3]);
    *(unsigned long long*)dh = H.u;
    *(unsigned long long*)dl = L.u;
}
__device__ __forceinline__ void store_split2(__nv_bfloat16* dh, __nv_bfloat16* dl, float a, float b) {
    union { __nv_bfloat16 b2[2]; uint32_t u; } H, L;
    split_bf16(a, H.b2[0], L.b2[0]);
    split_bf16(b, H.b2[1], L.b2[1]);
    *(uint32_t*)dh = H.u;
    *(uint32_t*)dl = L.u;
}
__device__ __forceinline__ float sigf(float x) { return 1.0f / (1.0f + expf(-x)); }

// SMEM tile geometry: 128 rows x 32 bf16, padded row stride 80B (conflict-free ldmatrix)
#define TROW 80
#define TBYTES (128 * TROW)        // 10240
#define STAGE (4 * TBYTES)         // Ah,Al,Bh,Bl
#define GSMEM (2 * STAGE)          // 81920

// async load of a [128 x 32] bf16 tile into padded SMEM; OOB rows -> zero fill
__device__ __forceinline__ void tile_async(uint32_t dst, const __nv_bfloat16* __restrict__ src,
                                           int stride, int row_base, int col_base,
                                           int row_limit, int t) {
#pragma unroll
    for (int i = 0; i < 2; i++) {
        int idx = t + i * 256;
        int r = idx >> 2, q = idx & 3;
        int gr = row_base + r;
        bool ok = gr < row_limit;
        int grc = ok ? gr : 0;
        const void* s = src + (size_t)grc * stride + col_base + q * 8;
        int sz = ok ? 16 : 0;
        asm volatile("cp.async.cg.shared.global [%0], [%1], 16, %2;"
                     :: "r"(dst + (uint32_t)(r * TROW + q * 16)), "l"(s), "r"(sz) : "memory");
    }
}

// ---------------- CSR construction ----------------
__global__ void k_zero() {
    int i = blockIdx.x * blockDim.x + threadIdx.x;
    if (i < NN) { g_deg[i] = 0; g_cursor[i] = 0; }
}
__global__ void k_count(const int* __restrict__ dst) {
    int e = blockIdx.x * blockDim.x + threadIdx.x;
    if (e < EE) atomicAdd(&g_deg[dst[e]], 1);
}
__global__ void k_scan_local() {
    int i = blockIdx.x * 1024 + threadIdx.x;
    int v = (i < NN) ? g_deg[i] : 0;
    int lane = threadIdx.x & 31, wid = threadIdx.x >> 5;
    int x = v;
#pragma unroll
    for (int o = 1; o < 32; o <<= 1) {
        int y = __shfl_up_sync(0xffffffffu, x, o);
        if (lane >= o) x += y;
    }
    __shared__ int ws[32];
    if (lane == 31) ws[wid] = x;
    __syncthreads();
    if (wid == 0) {
        int s = ws[lane];
        int xs = s;
#pragma unroll
        for (int o = 1; o < 32; o <<= 1) {
            int y = __shfl_up_sync(0xffffffffu, xs, o);
            if (lane >= o) xs += y;
        }
        ws[lane] = xs - s;
    }
    __syncthreads();
    int incl = x + ws[wid];
    if (i < NN) {
        g_rowptr[i] = incl - v;
        g_invdeg[i] = 1.0f / fmaxf((float)v, 1.0f);
    }
    if (threadIdx.x == 1023) g_chunksum[blockIdx.x] = incl;
}
__global__ void k_scan_mid() {
    if (threadIdx.x == 0) {
        int acc = 0;
        for (int c = 0; c < NCHUNK; c++) { g_chunkoff[c] = acc; acc += g_chunksum[c]; }
        g_rowptr[NN] = acc;
    }
}
__global__ void k_scan_add() {
    int i = blockIdx.x * 1024 + threadIdx.x;
    if (i < NN) g_rowptr[i] += g_chunkoff[blockIdx.x];
}
__global__ void k_fill(const int* __restrict__ src, const int* __restrict__ dst) {
    int e = blockIdx.x * blockDim.x + threadIdx.x;
    if (e < EE) {
        int d = dst[e];
        int p = atomicAdd(&g_cursor[d], 1);
        g_esrc[g_rowptr[d] + p] = src[e];
    }
}

// ---------------- weight packing (transposed, bf16 hi/lo) ----------------
__global__ void k_weights(const float* __restrict__ Wl, const float* __restrict__ Wr,
                          const float* __restrict__ b) {
    int i = blockIdx.x * blockDim.x + threadIdx.x;
    const int W1TN = LL * 384 * 512;
    const int W2TN = LL * 128 * 256;
    if (i < W1TN) {
        int l = i / (384 * 512);
        int rem = i % (384 * 512);
        int c = rem / 512, k = rem % 512;
        int cb = c >> 7, cc = c & 127;
        int s = k >> 7, kk = k & 127;
        float v = 0.0f;
        if (!(cb == 2 && s >= 2)) {
            int g = cb * 2 + (s >> 1);
            const float* W = (s & 1) ? Wr : Wl;
            v = W[(((size_t)l * 6 + g) * 128 + kk) * 128 + cc];
        }
        split_bf16(v, g_W1T_h[i], g_W1T_l[i]);
    } else if (i < W1TN + W2TN) {
        int j = i - W1TN;
        int l = j / (128 * 256);
        int rem = j % (128 * 256);
        int c = rem / 256, k = rem % 256;
        int s = k >> 7, kk = k & 127;
        const float* W = s ? Wr : Wl;
        float v = W[(((size_t)l * 6 + 5) * 128 + kk) * 128 + c];
        split_bf16(v, g_W2T_h[j], g_W2T_l[j]);
    } else if (i < W1TN + W2TN + LL * 384) {
        int j = i - W1TN - W2TN;
        int l = j / 384;
        int c = j % 384;
        int cb = c >> 7, cc = c & 127;
        g_bias[j] = b[(((size_t)l * 6 + cb * 2) * 128) + cc] +
                    b[(((size_t)l * 6 + cb * 2 + 1) * 128) + cc];
    }
}

// ---------------- fp32 -> bf16 hi/lo conversion (x only; h fused into agg2) ----------------
__global__ void k_conv(const float* __restrict__ src) {
    int i = blockIdx.x * blockDim.x + threadIdx.x;
    if (i >= NN * DD / 4) return;
    float4 v = __ldg((const float4*)src + i);
    store_split4(g_inp_h + (size_t)i * 4, g_inp_l + (size_t)i * 4, v);
}

// ---------------- aggregation (warp per dst node, atomic-free via CSR) ----------------
__global__ void k_agg2(const float* __restrict__ A, const float* __restrict__ B) {
    int warp = (blockIdx.x * blockDim.x + threadIdx.x) >> 5;
    int lane = threadIdx.x & 31;
    if (warp >= NN) return;
    int e = g_rowptr[warp], end = g_rowptr[warp + 1];
    float4 aa = make_float4(0.f, 0.f, 0.f, 0.f);
    float4 ab = make_float4(0.f, 0.f, 0.f, 0.f);
    for (; e + 1 < end; e += 2) {
        int s0 = g_esrc[e], s1 = g_esrc[e + 1];
        float4 va0 = __ldg((const float4*)(A + (size_t)s0 * DD) + lane);
        float4 vb0 = __ldg((const float4*)(B + (size_t)s0 * DD) + lane);
        float4 va1 = __ldg((const float4*)(A + (size_t)s1 * DD) + lane);
        float4 vb1 = __ldg((const float4*)(B + (size_t)s1 * DD) + lane);
        aa.x += va0.x + va1.x; aa.y += va0.y + va1.y;
        aa.z += va0.z + va1.z; aa.w += va0.w + va1.w;
        ab.x += vb0.x + vb1.x; ab.y += vb0.y + vb1.y;
        ab.z += vb0.z + vb1.z; ab.w += vb0.w + vb1.w;
    }
    if (e < end) {
        int s0 = g_esrc[e];
        float4 va0 = __ldg((const float4*)(A + (size_t)s0 * DD) + lane);
        float4 vb0 = __ldg((const float4*)(B + (size_t)s0 * DD) + lane);
        aa.x += va0.x; aa.y += va0.y; aa.z += va0.z; aa.w += va0.w;
        ab.x += vb0.x; ab.y += vb0.y; ab.z += vb0.z; ab.w += vb0.w;
    }
    float sc = g_invdeg[warp];
    aa.x *= sc; aa.y *= sc; aa.z *= sc; aa.w *= sc;
    ab.x *= sc; ab.y *= sc; ab.z *= sc; ab.w *= sc;
    size_t o = (size_t)warp * DD + lane * 4;
    store_split4(g_agga_h + o, g_agga_l + o, aa);
    store_split4(g_aggb_h + o, g_aggb_l + o, ab);
    // fused: split hl row for GEMM1's h operand segment
    float4 hv = __ldg((const float4*)(B + (size_t)warp * DD) + lane);
    store_split4(g_h_h + o, g_h_l + o, hv);
}

__global__ void k_agg1() {
    int warp = (blockIdx.x * blockDim.x + threadIdx.x) >> 5;
    int lane = threadIdx.x & 31;
    if (warp >= NN) return;
    int e = g_rowptr[warp], end = g_rowptr[warp + 1];
    float4 aa = make_float4(0.f, 0.f, 0.f, 0.f);
    for (; e + 1 < end; e += 2) {
        int s0 = g_esrc[e], s1 = g_esrc[e + 1];
        float4 va0 = __ldg((const float4*)(g_RH + (size_t)s0 * DD) + lane);
        float4 va1 = __ldg((const float4*)(g_RH + (size_t)s1 * DD) + lane);
        aa.x += va0.x + va1.x; aa.y += va0.y + va1.y;
        aa.z += va0.z + va1.z; aa.w += va0.w + va1.w;
    }
    if (e < end) {
        int s0 = g_esrc[e];
        float4 va0 = __ldg((const float4*)(g_RH + (size_t)s0 * DD) + lane);
        aa.x += va0.x; aa.y += va0.y; aa.z += va0.z; aa.w += va0.w;
    }
    float sc = g_invdeg[warp];
    aa.x *= sc; aa.y *= sc; aa.z *= sc; aa.w *= sc;
    size_t o = (size_t)warp * DD + lane * 4;
    store_split4(g_agga_h + o, g_agga_l + o, aa);
}

// ---------------- HMMA GEMM core ----------------
__device__ __forceinline__ void gemm_chunk(uint32_t sA_h, int t, float acc[2][8][4]) {
    uint32_t sA_l = sA_h + TBYTES;
    uint32_t sB_h = sA_h + 2 * TBYTES;
    uint32_t sB_l = sA_h + 3 * TBYTES;
    int lane = t & 31, wid = t >> 5;
    int wm = wid & 3, wn = wid >> 2;
    uint32_t rsel = (uint32_t)(lane & 15) * TROW + (uint32_t)(lane >> 4) * 16;

#pragma unroll
    for (int kb = 0; kb < 2; kb++) {
        uint32_t ko = kb * 32;
        uint32_t aoff = (uint32_t)(wm * 32) * TROW + rsel + ko;
        uint32_t boff = (uint32_t)(wn * 64) * TROW + rsel + ko;
        uint32_t Ah[2][4], Bh[4][4];
        ldsm4(Ah[0], sA_h + aoff);
        ldsm4(Ah[1], sA_h + aoff + 16 * TROW);
#pragma unroll
        for (int ng = 0; ng < 4; ng++) ldsm4(Bh[ng], sB_h + boff + ng * 16 * TROW);
#pragma unroll
        for (int mt = 0; mt < 2; mt++)
#pragma unroll
            for (int nt = 0; nt < 8; nt++) {
                int ng = nt >> 1, o = nt & 1;
                mma16816(acc[mt][nt], Ah[mt], Bh[ng][o], Bh[ng][o + 2]);
            }
        {
            uint32_t Bl[4][4];
#pragma unroll
            for (int ng = 0; ng < 4; ng++) ldsm4(Bl[ng], sB_l + boff + ng * 16 * TROW);
#pragma unroll
            for (int mt = 0; mt < 2; mt++)
#pragma unroll
                for (int nt = 0; nt < 8; nt++) {
                    int ng = nt >> 1, o = nt & 1;
                    mma16816(acc[mt][nt], Ah[mt], Bl[ng][o], Bl[ng][o + 2]);
                }
        }
        {
            uint32_t Al[2][4];
            ldsm4(Al[0], sA_l + aoff);
            ldsm4(Al[1], sA_l + aoff + 16 * TROW);
#pragma unroll
            for (int mt = 0; mt < 2; mt++)
#pragma unroll
                for (int nt = 0; nt < 8; nt++) {
                    int ng = nt >> 1, o = nt & 1;
                    mma16816(acc[mt][nt], Al[mt], Bh[ng][o], Bh[ng][o + 2]);
                }
        }
    }
}

// ---------------- GEMM1: [N,512]x[512,384] fused z / r*h / hx, cp.async pipelined ----------------
// cb==2 (hx) uses only K-segments {agg_inp, inp}: 8 chunks instead of 16 (rest of W1 is zero).
__global__ void __launch_bounds__(256, 2)
k_gemm1(const float* __restrict__ hl, int l) {
    extern __shared__ __align__(16) char smdyn[];
    uint32_t sb = smem_u32(smdyn);
    int t = threadIdx.x;
    int row0 = blockIdx.y * 128;
    int cb = blockIdx.x;
    int col0 = cb * 128;
    const int NC = (cb == 2) ? 8 : 16;

    const __nv_bfloat16* __restrict__ Wh = g_W1T_h + (size_t)l * 384 * 512;
    const __nv_bfloat16* __restrict__ Wlo = g_W1T_l + (size_t)l * 384 * 512;
    const __nv_bfloat16* segs_h[4] = { g_agga_h, g_inp_h, g_aggb_h, g_h_h };
    const __nv_bfloat16* segs_l[4] = { g_agga_l, g_inp_l, g_aggb_l, g_h_l };

    float acc[2][8][4];
#pragma unroll
    for (int i = 0; i < 2; i++)
#pragma unroll
        for (int j = 0; j < 8; j++)
#pragma unroll
            for (int q = 0; q < 4; q++) acc[i][j][q] = 0.0f;

    // prologue: chunk 0
    {
        uint32_t buf = sb;
        tile_async(buf,              segs_h[0], 128, row0, 0, NN, t);
        tile_async(buf + TBYTES,     segs_l[0], 128, row0, 0, NN, t);
        tile_async(buf + 2 * TBYTES, Wh,  512, col0, 0, 1 << 30, t);
        tile_async(buf + 3 * TBYTES, Wlo, 512, col0, 0, 1 << 30, t);
        CPA_COMMIT();
    }
    for (int c = 0; c < NC; c++) {
        if (c + 1 < NC) {
            int cn = c + 1;
            int seg = cn >> 2, colA = (cn & 3) * 32, colB = cn * 32;
            uint32_t buf = sb + (cn & 1) * STAGE;
            tile_async(buf,              segs_h[seg], 128, row0, colA, NN, t);
            tile_async(buf + TBYTES,     segs_l[seg], 128, row0, colA, NN, t);
            tile_async(buf + 2 * TBYTES, Wh,  512, col0, colB, 1 << 30, t);
            tile_async(buf + 3 * TBYTES, Wlo, 512, col0, colB, 1 << 30, t);
        }
        CPA_COMMIT();
        CPA_WAIT1();
        __syncthreads();
        gemm_chunk(sb + (c & 1) * STAGE, t, acc);
        __syncthreads();
    }

    // epilogue
    int lane = t & 31, wid = t >> 5;
    int wm = wid & 3, wn = wid >> 2;
    const float* bias = g_bias + l * 384;
#pragma unroll
    for (int mt = 0; mt < 2; mt++)
#pragma unroll
        for (int nt = 0; nt < 8; nt++) {
            int row = row0 + wm * 32 + mt * 16 + (lane >> 2);
            int col = col0 + wn * 64 + nt * 8 + (lane & 3) * 2;
            float b0 = __ldg(bias + col), b1 = __ldg(bias + col + 1);
            int ccol = col & 127;
#pragma unroll
            for (int half = 0; half < 2; half++) {
                int r = row + half * 8;
                if (r >= NN) continue;
                float v0 = acc[mt][nt][half * 2 + 0] + b0;
                float v1 = acc[mt][nt][half * 2 + 1] + b1;
                size_t idx = (size_t)r * 128 + ccol;
                if (cb == 0) {
                    float2 z = make_float2(sigf(v0), sigf(v1));
                    *(float2*)(g_Z + idx) = z;
                } else if (cb == 1) {
                    float h0 = hl[idx], h1 = hl[idx + 1];
                    float rh0 = sigf(v0) * h0, rh1 = sigf(v1) * h1;
                    *(float2*)(g_RH + idx) = make_float2(rh0, rh1);
                    store_split2(g_rh_h + idx, g_rh_l + idx, rh0, rh1);
                } else {
                    *(float2*)(g_HX + idx) = make_float2(v0, v1);
                }
            }
        }
}

// ---------------- GEMM2: [N,256]x[256,128] fused GRU mix, cp.async pipelined ----------------
__global__ void __launch_bounds__(256, 2)
k_gemm2(const float* __restrict__ hl, float* __restrict__ out, int l) {
    extern __shared__ __align__(16) char smdyn[];
    uint32_t sb = smem_u32(smdyn);
    int t = threadIdx.x;
    int row0 = blockIdx.y * 128;

    const __nv_bfloat16* __restrict__ Wh = g_W2T_h + (size_t)l * 128 * 256;
    const __nv_bfloat16* __restrict__ Wlo = g_W2T_l + (size_t)l * 128 * 256;
    const __nv_bfloat16* segs_h[2] = { g_agga_h, g_rh_h };
    const __nv_bfloat16* segs_l[2] = { g_agga_l, g_rh_l };

    float acc[2][8][4];
#pragma unroll
    for (int i = 0; i < 2; i++)
#pragma unroll
        for (int j = 0; j < 8; j++)
#pragma unroll
            for (int q = 0; q < 4; q++) acc[i][j][q] = 0.0f;

    {
        uint32_t buf = sb;
        tile_async(buf,              segs_h[0], 128, row0, 0, NN, t);
        tile_async(buf + TBYTES,     segs_l[0], 128, row0, 0, NN, t);
        tile_async(buf + 2 * TBYTES, Wh,  256, 0, 0, 1 << 30, t);
        tile_async(buf + 3 * TBYTES, Wlo, 256, 0, 0, 1 << 30, t);
        CPA_COMMIT();
    }
    for (int c = 0; c < 8; c++) {
        if (c + 1 < 8) {
            int cn = c + 1;
            int seg = cn >> 2, colA = (cn & 3) * 32, colB = cn * 32;
            uint32_t buf = sb + (cn & 1) * STAGE;
            tile_async(buf,              segs_h[seg], 128, row0, colA, NN, t);
            tile_async(buf + TBYTES,     segs_l[seg], 128, row0, colA, NN, t);
            tile_async(buf + 2 * TBYTES, Wh,  256, 0, colB, 1 << 30, t);
            tile_async(buf + 3 * TBYTES, Wlo, 256, 0, colB, 1 << 30, t);
        }
        CPA_COMMIT();
        CPA_WAIT1();
        __syncthreads();
        gemm_chunk(sb + (c & 1) * STAGE, t, acc);
        __syncthreads();
    }

    int lane = t & 31, wid = t >> 5;
    int wm = wid & 3, wn = wid >> 2;
#pragma unroll
    for (int mt = 0; mt < 2; mt++)
#pragma unroll
        for (int nt = 0; nt < 8; nt++) {
            int row = row0 + wm * 32 + mt * 16 + (lane >> 2);
            int col = wn * 64 + nt * 8 + (lane & 3) * 2;
#pragma unroll
            for (int half = 0; half < 2; half++) {
                int r = row + half * 8;
                if (r >= NN) continue;
                size_t idx = (size_t)r * 128 + col;
                float hx0 = g_HX[idx], hx1 = g_HX[idx + 1];
                float z0 = g_Z[idx], z1 = g_Z[idx + 1];
                float h0 = hl[idx], h1 = hl[idx + 1];
                float ht0 = tanhf(acc[mt][nt][half * 2 + 0] + hx0);
                float ht1 = tanhf(acc[mt][nt][half * 2 + 1] + hx1);
                float o0 = z0 * h0 + (1.0f - z0) * ht0;
                float o1 = z1 * h1 + (1.0f - z1) * ht1;
                *(float2*)(out + idx) = make_float2(o0, o1);
                store_split2(g_inp_h + idx, g_inp_l + idx, o0, o1);
            }
        }
}

// ---------------- launch ----------------
extern "C" void kernel_launch(void* const* d_in, const int* in_sizes, int n_in,
                              void* d_out, int out_size) {
    const float* x  = (const float*)d_in[0];
    const float* h  = (const float*)d_in[1];
    const float* Wl = (const float*)d_in[2];
    const float* Wr = (const float*)d_in[3];
    const float* b  = (const float*)d_in[4];
    const int* src  = (const int*)d_in[5];
    const int* dst  = (const int*)d_in[6];
    float* out = (float*)d_out;

    cudaFuncSetAttribute(k_gemm1, cudaFuncAttributeMaxDynamicSharedMemorySize, GSMEM);
    cudaFuncSetAttribute(k_gemm2, cudaFuncAttributeMaxDynamicSharedMemorySize, GSMEM);

    // CSR build
    k_zero<<<(NN + 255) / 256, 256>>>();
    k_count<<<(EE + 255) / 256, 256>>>(dst);
    k_scan_local<<<NCHUNK, 1024>>>();
    k_scan_mid<<<1, 32>>>();
    k_scan_add<<<NCHUNK, 1024>>>();
    k_fill<<<(EE + 255) / 256, 256>>>(src, dst);

    // weights (transposed bf16 hi/lo) + biases
    const int WTOT = LL * 384 * 512 + LL * 128 * 256 + LL * 384;
    k_weights<<<(WTOT + 255) / 256, 256>>>(Wl, Wr, b);

    // x -> inp hi/lo for layer 0
    k_conv<<<(NN * DD / 4 + 255) / 256, 256>>>(x);

    const int ROWT = (NN + 127) / 128;
    for (int l = 0; l < LL; l++) {
        const float* inp = (l == 0) ? x : (out + (size_t)(l - 1) * NN * DD);
        const float* hl = h + (size_t)l * NN * DD;
        k_agg2<<<(NN * 32 + 255) / 256, 256>>>(inp, hl);
        dim3 g1(3, ROWT);
        k_gemm1<<<g1, 256, GSMEM>>>(hl, l);
        k_agg1<<<(NN * 32 + 255) / 256, 256>>>();
        dim3 g2(1, ROWT);
        k_gemm2<<<g2, 256, GSMEM>>>(hl, out + (size_t)l * NN * DD, l);
    }
}